// round 16
// baseline (speedup 1.0000x reference)
#include <cuda_runtime.h>
#include <cstdint>
#include <cstdio>

#define HID 256
#define HS  512
#define NH  8
#define HD  64
#define NTOK 8
#define BB  8

__device__ float g_u[BB][NH][HID];
__device__ float g_s1[BB][HS];
__device__ float g_qh[BB][HS];
// Duplicated v-weights: g_wdup[e][ch][d] as (v,v) float pairs.  1 MB
__device__ float g_wdup[NH * HID * HD * 2];
// Intermediate h, ed-major: g_h[ed][pix], pix = b*1024 + hrow*32 + w.  16.8 MB
__device__ float g_h[HS * 8192];

static __device__ __forceinline__ unsigned long long pk2(float lo, float hi){
  unsigned long long r; asm("mov.b64 %0, {%1,%2};" : "=l"(r) : "f"(lo), "f"(hi)); return r;
}
static __device__ __forceinline__ void upk2(unsigned long long v, float& lo, float& hi){
  asm("mov.b64 {%0,%1}, %2;" : "=f"(lo), "=f"(hi) : "l"(v));
}
static __device__ __forceinline__ unsigned long long f2fma(unsigned long long a, unsigned long long b, unsigned long long c){
  unsigned long long d; asm("fma.rn.f32x2 %0, %1, %2, %3;" : "=l"(d) : "l"(a), "l"(b), "l"(c)); return d;
}
static __device__ __forceinline__ unsigned long long f2mul(unsigned long long a, unsigned long long b){
  unsigned long long d; asm("mul.rn.f32x2 %0, %1, %2;" : "=l"(d) : "l"(a), "l"(b)); return d;
}

// ---------------- setup stage 1: s1 = silu(emb[q] @ w1 + b1)   grid (8 b, 8 slice), 256 thr
__global__ void setup_s1(const int* __restrict__ q, const float* __restrict__ emb,
                         const float* __restrict__ w1, const float* __restrict__ b1)
{
  __shared__ float red[4][64];
  __shared__ float qe[HID];
  const int b = blockIdx.x, slice = blockIdx.y, t = threadIdx.x;
  if (t < HID) qe[t] = __ldg(emb + (size_t)__ldg(q + b)*HID + t);
  __syncthreads();
  const int cl = t & 63, qq = t >> 6;
  const int col = slice*64 + cl;
  const float* wcol = w1 + col;
  float a0=0.f, a1=0.f;
  const int i0 = qq*64;
  #pragma unroll 8
  for (int i=0; i<64; i+=2){
    a0 = fmaf(qe[i0+i  ], __ldg(wcol + (size_t)(i0+i  )*HS), a0);
    a1 = fmaf(qe[i0+i+1], __ldg(wcol + (size_t)(i0+i+1)*HS), a1);
  }
  red[qq][cl] = a0 + a1;
  __syncthreads();
  if (t < 64){
    float s = red[0][t]+red[1][t]+red[2][t]+red[3][t] + __ldg(b1 + slice*64 + t);
    g_s1[b][slice*64+t] = s / (1.f + expf(-s));
  }
}

// ---------------- setup stage 2: qh = s1 @ w2 + b2   grid (8 b, 8 slice), 256 thr
__global__ void setup_qh(const float* __restrict__ w2, const float* __restrict__ b2)
{
  __shared__ float red[4][64];
  __shared__ float s1s[HS];
  const int b = blockIdx.x, slice = blockIdx.y, t = threadIdx.x;
  s1s[t]     = g_s1[b][t];
  s1s[t+256] = g_s1[b][t+256];
  __syncthreads();
  const int cl = t & 63, qq = t >> 6;
  const int col = slice*64 + cl;
  const float* wcol = w2 + col;
  float a0=0.f, a1=0.f;
  const int i0 = qq*128;
  #pragma unroll 8
  for (int i=0; i<128; i+=2){
    a0 = fmaf(s1s[i0+i  ], __ldg(wcol + (size_t)(i0+i  )*HS), a0);
    a1 = fmaf(s1s[i0+i+1], __ldg(wcol + (size_t)(i0+i+1)*HS), a1);
  }
  red[qq][cl] = a0 + a1;
  __syncthreads();
  if (t < 64)
    g_qh[b][slice*64+t] = red[0][t]+red[1][t]+red[2][t]+red[3][t] + __ldg(b2 + slice*64 + t);
}

// ---------------- setup stage 3: u[b][e][ch] = (w_kv_k[ch,e,:] . qh[b,e,:]) * rms_w[ch]/8
__global__ void setup_u(const float* __restrict__ w_kv, const float* __restrict__ rms_w)
{
  __shared__ float qh_sm[64];
  const int b = blockIdx.x, e = blockIdx.y, t = threadIdx.x;
  if (t < 64) qh_sm[t] = g_qh[b][e*64 + t];
  __syncthreads();
  const float4* wk = reinterpret_cast<const float4*>(w_kv + (size_t)t*1024 + e*128);
  float a0=0.f, a1=0.f;
  #pragma unroll
  for (int j=0; j<16; j+=2){
    float4 v0 = __ldg(wk + j);
    float4 v1 = __ldg(wk + j + 1);
    a0 = fmaf(qh_sm[4*j+0], v0.x, a0);
    a0 = fmaf(qh_sm[4*j+1], v0.y, a0);
    a0 = fmaf(qh_sm[4*j+2], v0.z, a0);
    a0 = fmaf(qh_sm[4*j+3], v0.w, a0);
    a1 = fmaf(qh_sm[4*j+4], v1.x, a1);
    a1 = fmaf(qh_sm[4*j+5], v1.y, a1);
    a1 = fmaf(qh_sm[4*j+6], v1.z, a1);
    a1 = fmaf(qh_sm[4*j+7], v1.w, a1);
  }
  g_u[b][e][t] = (a0+a1) * __ldg(rms_w + t) * 0.125f;
}

// ---------------- setup stage 4: duplicate v-weights.  grid (8 e, 8 cg), 256 thr, coalesced
__global__ void wdup_build(const float* __restrict__ w_kv)
{
  const int e = blockIdx.x, cg = blockIdx.y, t = threadIdx.x;
  const int ch_l = t >> 3, part = t & 7;   // 32 ch x 8 parts (8 d each)
  const int ch = cg*32 + ch_l;
  const float4* src = reinterpret_cast<const float4*>(
      w_kv + (size_t)ch*1024 + e*128 + 64 + part*8);
  float4 a = __ldg(src);
  float4 bq = __ldg(src + 1);
  float4* dst = reinterpret_cast<float4*>(
      g_wdup + (((size_t)e*HID + ch)*HD + part*8)*2);
  dst[0] = make_float4(a.x, a.x, a.y, a.y);
  dst[1] = make_float4(a.z, a.z, a.w, a.w);
  dst[2] = make_float4(bq.x, bq.x, bq.y, bq.y);
  dst[3] = make_float4(bq.z, bq.z, bq.w, bq.w);
}

// ---------------- kernel1: pass1 + softmax + g + h -> g_h (ed-major)
// smem (floats), 21504 total = 86KB -> 2 blocks/SM:
//  [0,256)        rms
//  [256,512)      rinv [n][w]
//  [512,2560)     attn (pass1 dots, e-major; dead after softmax)
//  [2560,5120)    attn2 [nn][w*10 + e]  (packed-pair layout, pad stride 10)
//  [5120,13312)   cn   [n][cc][w]   (ur aliases first 2048 during pass 1)
//  [13312,21504)  g    [e][cc][w]
__global__ __launch_bounds__(256, 2) void main_kernel(const float* __restrict__ c,
    const float* __restrict__ rms_w, const float* __restrict__ w_kv)
{
  extern __shared__ float sm[];
  float* rms_sm   = sm;
  float* rinv_sm  = sm + 256;
  float* attn_sm  = sm + 512;
  float* attn2_sm = sm + 2560;
  float* cn_sm    = sm + 5120;
  float* ur_sm    = sm + 5120;   // alias (dead once chunk loop starts)
  float* g_sm     = sm + 13312;

  const int t  = threadIdx.x;
  const int bx = blockIdx.x;
  const int b  = bx >> 5, hrow = bx & 31;
  const int w  = t & 31;
  const int n  = t >> 5;        // warp id
  const int lane = w;

  rms_sm[t] = rms_w[t];
  {
    int ch = t;
    #pragma unroll
    for (int e=0;e<NH;e++) ur_sm[ch*NH + e] = g_u[b][e][ch];
  }
  __syncthreads();

  const float* cp = c + ((size_t)(b*NTOK + n)*HID)*1024 + hrow*32 + w;

  // ---- pass 1: stream c once (unroll-8 batched loads); rms sum + 8 head dots
  float ss = 0.f;
  unsigned long long s2[4];
  s2[0]=s2[1]=s2[2]=s2[3]=0ull;
  const unsigned long long* urp = reinterpret_cast<const unsigned long long*>(ur_sm);
  for (int c8=0; c8<32; c8++){
    float x[8];
    #pragma unroll
    for (int j=0;j<8;j++) x[j] = __ldg(cp + (size_t)(c8*8+j)*1024);
    #pragma unroll
    for (int j=0;j<8;j++){
      unsigned long long xd = pk2(x[j],x[j]);
      int ch = c8*8+j;
      ss = fmaf(x[j],x[j],ss);
      s2[0] = f2fma(xd, urp[ch*4+0], s2[0]);
      s2[1] = f2fma(xd, urp[ch*4+1], s2[1]);
      s2[2] = f2fma(xd, urp[ch*4+2], s2[2]);
      s2[3] = f2fma(xd, urp[ch*4+3], s2[3]);
    }
  }
  float rinv = rsqrtf(ss*(1.f/256.f) + 1e-6f);
  rinv_sm[n*32+w] = rinv;
  #pragma unroll
  for (int j=0;j<4;j++){
    float lo,hi; upk2(s2[j],lo,hi);
    attn_sm[(2*j  )*256 + n*32 + w] = lo*rinv;
    attn_sm[(2*j+1)*256 + n*32 + w] = hi*rinv;
  }
  __syncthreads();

  // ---- softmax over n: thread (e = n-slot, w); writes packed layout attn2[nn][w*10+e]
  {
    int e = n;
    float d[8], m = -1e30f;
    #pragma unroll
    for (int i=0;i<8;i++){ d[i] = attn_sm[e*256 + i*32 + w]; m = fmaxf(m,d[i]); }
    float ssum = 0.f;
    #pragma unroll
    for (int i=0;i<8;i++){ d[i] = __expf(d[i]-m); ssum += d[i]; }
    float inv = 1.f/ssum;
    #pragma unroll
    for (int i=0;i<8;i++) attn2_sm[i*320 + w*10 + e] = d[i]*inv;
  }
  __syncthreads();

  // ---- cn-stage vector remap: lane = (pq = lane&7 pixel-quad, cb = lane>>3 cc-block)
  const int pq = lane & 7;
  const int cb = lane >> 3;
  unsigned long long rp0, rp1;
  {
    const unsigned long long* rq =
        reinterpret_cast<const unsigned long long*>(rinv_sm + n*32 + 4*pq);
    rp0 = rq[0];
    rp1 = rq[1];
  }
  const float4* c4 = reinterpret_cast<const float4*>(
      c + ((size_t)(b*NTOK + n)*HID)*1024 + hrow*32 + 4*pq);   // + ch*256 float4 per channel

  // ---- chunk loop.  h-phase tile: warp = head e; thread (dg = lane&7, wpg = lane>>3):
  //   d in [dg*8, dg*8+8) via pre-dup'd pairs, 4 consecutive w-PAIRS (pixels 8wpg..8wpg+7)
  const int e   = n;
  const int dg  = lane & 7;
  const int wpg = lane >> 3;            // 0..3
  const int d0  = dg * 8;
  unsigned long long hacc[8][4];        // [d][k], k = pixel pair (8wpg+2k, +1)
  #pragma unroll
  for (int i=0;i<8;i++){
    #pragma unroll
    for (int k=0;k<4;k++) hacc[i][k]=0ull;
  }
  // dup'd weights: row = (e*256+ch)*128 floats = 32 ull2; this thread's slice at +d0*2 floats
  const ulonglong2* wvd = reinterpret_cast<const ulonglong2*>(
      g_wdup + ((size_t)e*HID*HD + (size_t)d0)*2);

  for (int kc=0; kc<8; kc++){
    const int ch0 = kc*32;
    // stage normalized c chunk, vectorized: 8 iters, each = LDG128 + 4 f32x2 mul + STS128
    {
      #pragma unroll
      for (int i=0; i<8; i++){
        const int cc = cb*8 + i;
        float4 x4 = __ldg(c4 + (size_t)(ch0+cc)*256);
        float rmsv = rms_sm[ch0+cc];
        unsigned long long rmsd = pk2(rmsv, rmsv);
        unsigned long long x01 = pk2(x4.x, x4.y);
        unsigned long long x23 = pk2(x4.z, x4.w);
        unsigned long long cn01 = f2mul(f2mul(x01, rp0), rmsd);
        unsigned long long cn23 = f2mul(f2mul(x23, rp1), rmsd);
        ulonglong2 v; v.x = cn01; v.y = cn23;
        *reinterpret_cast<ulonglong2*>(cn_sm + n*1024 + cc*32 + 4*pq) = v;
      }
    }
    __syncthreads();
    // g-phase: thread (ccg=n, w) does 4 cc, all e via packed e-pairs
    {
      int ccg = n;
      unsigned long long gap[4][4];   // [e-pair][j2]
      #pragma unroll
      for (int i=0;i<4;i++){
        #pragma unroll
        for (int j2=0;j2<4;j2++) gap[i][j2]=0ull;
      }
      #pragma unroll
      for (int nn=0; nn<8; nn++){
        const unsigned long long* ap =
            reinterpret_cast<const unsigned long long*>(attn2_sm + nn*320 + w*10);
        unsigned long long a01 = ap[0], a23 = ap[1], a45 = ap[2], a67 = ap[3];
        #pragma unroll
        for (int j2=0;j2<4;j2++){
          float cv = cn_sm[nn*1024 + (ccg*4+j2)*32 + w];
          unsigned long long cnd = pk2(cv,cv);
          gap[0][j2] = f2fma(a01, cnd, gap[0][j2]);
          gap[1][j2] = f2fma(a23, cnd, gap[1][j2]);
          gap[2][j2] = f2fma(a45, cnd, gap[2][j2]);
          gap[3][j2] = f2fma(a67, cnd, gap[3][j2]);
        }
      }
      #pragma unroll
      for (int eep=0;eep<4;eep++){
        #pragma unroll
        for (int j2=0;j2<4;j2++){
          float lo,hi; upk2(gap[eep][j2],lo,hi);
          g_sm[(2*eep  )*1024 + (ccg*4+j2)*32 + w] = lo;
          g_sm[(2*eep+1)*1024 + (ccg*4+j2)*32 + w] = hi;
        }
      }
    }
    __syncthreads();
    // h-phase: per cc = 4 LDG128 (pre-dup'd d-pair weights) + 4 LDS64 (w-pairs) + 32 FFMA2
    {
      const unsigned long long* gbase =
          reinterpret_cast<const unsigned long long*>(g_sm + e*1024) + 4*wpg;
      #pragma unroll 2
      for (int cc=0; cc<32; cc++){
        const int ch = ch0 + cc;
        const ulonglong2* wp = wvd + (size_t)ch*32;
        ulonglong2 q0 = __ldg(wp+0);
        ulonglong2 q1 = __ldg(wp+1);
        ulonglong2 q2 = __ldg(wp+2);
        ulonglong2 q3 = __ldg(wp+3);
        const unsigned long long* gp = gbase + cc*16;
        unsigned long long g0 = gp[0], g1 = gp[1], g2v = gp[2], g3 = gp[3];
        hacc[0][0]=f2fma(q0.x,g0,hacc[0][0]); hacc[0][1]=f2fma(q0.x,g1,hacc[0][1]);
        hacc[0][2]=f2fma(q0.x,g2v,hacc[0][2]); hacc[0][3]=f2fma(q0.x,g3,hacc[0][3]);
        hacc[1][0]=f2fma(q0.y,g0,hacc[1][0]); hacc[1][1]=f2fma(q0.y,g1,hacc[1][1]);
        hacc[1][2]=f2fma(q0.y,g2v,hacc[1][2]); hacc[1][3]=f2fma(q0.y,g3,hacc[1][3]);
        hacc[2][0]=f2fma(q1.x,g0,hacc[2][0]); hacc[2][1]=f2fma(q1.x,g1,hacc[2][1]);
        hacc[2][2]=f2fma(q1.x,g2v,hacc[2][2]); hacc[2][3]=f2fma(q1.x,g3,hacc[2][3]);
        hacc[3][0]=f2fma(q1.y,g0,hacc[3][0]); hacc[3][1]=f2fma(q1.y,g1,hacc[3][1]);
        hacc[3][2]=f2fma(q1.y,g2v,hacc[3][2]); hacc[3][3]=f2fma(q1.y,g3,hacc[3][3]);
        hacc[4][0]=f2fma(q2.x,g0,hacc[4][0]); hacc[4][1]=f2fma(q2.x,g1,hacc[4][1]);
        hacc[4][2]=f2fma(q2.x,g2v,hacc[4][2]); hacc[4][3]=f2fma(q2.x,g3,hacc[4][3]);
        hacc[5][0]=f2fma(q2.y,g0,hacc[5][0]); hacc[5][1]=f2fma(q2.y,g1,hacc[5][1]);
        hacc[5][2]=f2fma(q2.y,g2v,hacc[5][2]); hacc[5][3]=f2fma(q2.y,g3,hacc[5][3]);
        hacc[6][0]=f2fma(q3.x,g0,hacc[6][0]); hacc[6][1]=f2fma(q3.x,g1,hacc[6][1]);
        hacc[6][2]=f2fma(q3.x,g2v,hacc[6][2]); hacc[6][3]=f2fma(q3.x,g3,hacc[6][3]);
        hacc[7][0]=f2fma(q3.y,g0,hacc[7][0]); hacc[7][1]=f2fma(q3.y,g1,hacc[7][1]);
        hacc[7][2]=f2fma(q3.y,g2v,hacc[7][2]); hacc[7][3]=f2fma(q3.y,g3,hacc[7][3]);
      }
    }
    __syncthreads();
  }

  // ---- write h to global, ed-major: 8 consecutive pixels per thread -> 2x STG128 per d row
  {
    const int pixb = b*1024 + hrow*32 + 8*wpg;
    #pragma unroll
    for (int d=0; d<8; d++){
      int ed = e*64 + d0 + d;
      float* r = g_h + (size_t)ed*8192 + pixb;
      ulonglong2 v0; v0.x = hacc[d][0]; v0.y = hacc[d][1];
      ulonglong2 v1; v1.x = hacc[d][2]; v1.y = hacc[d][3];
      *reinterpret_cast<ulonglong2*>(r)     = v0;
      *reinterpret_cast<ulonglong2*>(r + 4) = v1;
    }
  }
}

// ---------------- kernel2 (R10, FROZEN): out[pix, o] = h[pix, :] @ w_out + b_out
// M=8192, N=256, K=512.  Block tile 128M x 64N, grid (64, 4), 256 threads.
__global__ __launch_bounds__(256) void out_gemm(const float* __restrict__ w_out,
                                                const float* __restrict__ b_out,
                                                float* __restrict__ out)
{
  __shared__ float a_sm[32*128];   // [kk][m]
  __shared__ float b_sm[32*64];    // [kk][n]
  const int t = threadIdx.x;
  const int Mbase = blockIdx.x * 128;
  const int Nbase = blockIdx.y * 64;
  const int mg = t & 15, ng = t >> 4;

  unsigned long long acc[4][4];
  #pragma unroll
  for (int j=0;j<4;j++){
    #pragma unroll
    for (int nn=0;nn<4;nn++) acc[j][nn]=0ull;
  }

  float4 ra[4], rb[2];
  #pragma unroll
  for (int i=0;i<4;i++){
    int l = i*256 + t, kk = l >> 5, mf = l & 31;
    ra[i] = __ldg(reinterpret_cast<const float4*>(g_h + (size_t)kk*8192 + Mbase + mf*4));
  }
  #pragma unroll
  for (int i=0;i<2;i++){
    int l = i*256 + t, kk = l >> 4, nf = l & 15;
    rb[i] = __ldg(reinterpret_cast<const float4*>(w_out + (size_t)kk*256 + Nbase + nf*4));
  }

  for (int kc=0; kc<16; kc++){
    #pragma unroll
    for (int i=0;i<4;i++){
      int l = i*256 + t, kk = l >> 5, mf = l & 31;
      *reinterpret_cast<float4*>(a_sm + kk*128 + mf*4) = ra[i];
    }
    #pragma unroll
    for (int i=0;i<2;i++){
      int l = i*256 + t, kk = l >> 4, nf = l & 15;
      *reinterpret_cast<float4*>(b_sm + kk*64 + nf*4) = rb[i];
    }
    __syncthreads();
    if (kc < 15){
      int k0 = (kc+1)*32;
      #pragma unroll
      for (int i=0;i<4;i++){
        int l = i*256 + t, kk = l >> 5, mf = l & 31;
        ra[i] = __ldg(reinterpret_cast<const float4*>(g_h + (size_t)(k0+kk)*8192 + Mbase + mf*4));
      }
      #pragma unroll
      for (int i=0;i<2;i++){
        int l = i*256 + t, kk = l >> 4, nf = l & 15;
        rb[i] = __ldg(reinterpret_cast<const float4*>(w_out + (size_t)(k0+kk)*256 + Nbase + nf*4));
      }
    }
    #pragma unroll 4
    for (int kk=0; kk<32; kk++){
      unsigned long long am[4];
      #pragma unroll
      for (int j=0;j<4;j++)
        am[j] = *reinterpret_cast<const unsigned long long*>(a_sm + kk*128 + 2*mg + 32*j);
      #pragma unroll
      for (int nn=0;nn<4;nn++){
        float bv = b_sm[kk*64 + ng*4 + nn];
        unsigned long long bd = pk2(bv,bv);
        #pragma unroll
        for (int j=0;j<4;j++) acc[j][nn] = f2fma(am[j], bd, acc[j][nn]);
      }
    }
    __syncthreads();
  }

  const int bb = Mbase >> 10;
  const int pl = (Mbase & 1023) + 2*mg;
  #pragma unroll
  for (int nn=0;nn<4;nn++){
    int o = Nbase + ng*4 + nn;
    float bo = __ldg(b_out + o);
    float* op = out + (size_t)bb*262144 + (size_t)o*1024 + pl;
    #pragma unroll
    for (int j=0;j<4;j++){
      float lo,hi; upk2(acc[j][nn],lo,hi);
      float2 v = make_float2(lo+bo, hi+bo);
      *reinterpret_cast<float2*>(op + 32*j) = v;
    }
  }
}

extern "C" void kernel_launch(void* const* d_in, const int* in_sizes, int n_in,
                              void* d_out, int out_size) {
  const int*   q     = (const int*)  d_in[0];
  const float* c     = (const float*)d_in[1];
  const float* rms_w = (const float*)d_in[2];
  const float* emb   = (const float*)d_in[3];
  const float* w1    = (const float*)d_in[4];
  const float* b1    = (const float*)d_in[5];
  const float* w2    = (const float*)d_in[6];
  const float* b2    = (const float*)d_in[7];
  const float* w_kv  = (const float*)d_in[8];
  const float* w_out = (const float*)d_in[9];
  const float* b_out = (const float*)d_in[10];
  float* out = (float*)d_out;

  wdup_build<<<dim3(NH, 8), 256>>>(w_kv);
  setup_s1<<<dim3(BB, 8), 256>>>(q, emb, w1, b1);
  setup_qh<<<dim3(BB, 8), 256>>>(w2, b2);
  setup_u <<<dim3(BB, NH), 256>>>(w_kv, rms_w);

  int smem_bytes = 21504 * 4;  // 86KB -> 2 blocks/SM
  cudaFuncSetAttribute(main_kernel, cudaFuncAttributeMaxDynamicSharedMemorySize, smem_bytes);
  main_kernel<<<256, 256, smem_bytes>>>(c, rms_w, w_kv);

  out_gemm<<<dim3(64, 4), 256>>>(w_out, b_out, out);
}